// round 12
// baseline (speedup 1.0000x reference)
#include <cuda_runtime.h>
#include <math_constants.h>
#include <cstdint>
#include <cstddef>

// Problem shape (fixed by the reference)
#define BB 64
#define TT 4096
#define DD 512
#define ROWS (BB * TT)          // 262144 flattened (b,t) rows
#define NWARP 8
#define MAXG 512                // upper bound on persistent grid size

// Device scratch (allocation-free contract: __device__ globals)
__device__ float        g_k[BB * DD];                    // projected keys
__device__ float        g_pm[MAXG * 2];                  // per-(block,seg) max
__device__ float        g_ps[MAXG * 2];                  // per-(block,seg) sum
__device__ float        g_pctx[(size_t)MAXG * 2 * DD];   // per-(block,seg) ctx (2 MB)
__device__ unsigned int g_cnt[BB];                       // per-batch arrival count

// ---------------------------------------------------------------------------
// Setup kernel: block-per-batch GEMV. q[b,:] staged in smem ONCE (no syncs in
// the row loop); warp w streams rows d = w*64..w*64+63 of W with coalesced
// float4 loads, 2-row unroll for MLP. W (1 MB) is L2-resident after the
// first wave. Also resets combine counters for graph replay.
// ---------------------------------------------------------------------------
__global__ void __launch_bounds__(256) setup_kernel(
    const float* __restrict__ q, const float* __restrict__ W,
    const float* __restrict__ bias)
{
    __shared__ float qs[DD];
    const int b    = blockIdx.x;
    const int tid  = threadIdx.x;
    const int w    = tid >> 5;
    const int lane = tid & 31;

    if (b == 0 && tid < BB) g_cnt[tid] = 0u;   // reset for every graph replay

    qs[tid]       = q[b * DD + tid];
    qs[tid + 256] = q[b * DD + tid + 256];
    __syncthreads();

    const float4 q0 = *(const float4*)&qs[lane * 4];
    const float4 q1 = *(const float4*)&qs[lane * 4 + 128];
    const float4 q2 = *(const float4*)&qs[lane * 4 + 256];
    const float4 q3 = *(const float4*)&qs[lane * 4 + 384];

#define DOTROW(DV, OUTV)                                                      \
    {   const float* _wr = W + (size_t)(DV) * DD + lane * 4;                  \
        const float4 w0 = *(const float4*)(_wr);                              \
        const float4 w1 = *(const float4*)(_wr + 128);                        \
        const float4 w2 = *(const float4*)(_wr + 256);                        \
        const float4 w3 = *(const float4*)(_wr + 384);                        \
        float v = w0.x * q0.x;                                                \
        v = fmaf(w0.y, q0.y, v); v = fmaf(w0.z, q0.z, v);                     \
        v = fmaf(w0.w, q0.w, v);                                              \
        v = fmaf(w1.x, q1.x, v); v = fmaf(w1.y, q1.y, v);                     \
        v = fmaf(w1.z, q1.z, v); v = fmaf(w1.w, q1.w, v);                     \
        v = fmaf(w2.x, q2.x, v); v = fmaf(w2.y, q2.y, v);                     \
        v = fmaf(w2.z, q2.z, v); v = fmaf(w2.w, q2.w, v);                     \
        v = fmaf(w3.x, q3.x, v); v = fmaf(w3.y, q3.y, v);                     \
        v = fmaf(w3.z, q3.z, v); v = fmaf(w3.w, q3.w, v);                     \
        v += __shfl_xor_sync(0xffffffffu, v, 16);                             \
        v += __shfl_xor_sync(0xffffffffu, v, 8);                              \
        v += __shfl_xor_sync(0xffffffffu, v, 4);                              \
        v += __shfl_xor_sync(0xffffffffu, v, 2);                              \
        v += __shfl_xor_sync(0xffffffffu, v, 1);                              \
        OUTV = v; }

    const int d0base = w * 64;
    for (int i = 0; i < 64; i += 2) {          // 2 independent rows -> MLP
        float va, vb;
        DOTROW(d0base + i,     va);
        DOTROW(d0base + i + 1, vb);
        if (lane == 0) {
            g_k[b * DD + d0base + i]     = va + bias[d0base + i];
            g_k[b * DD + d0base + i + 1] = vb + bias[d0base + i + 1];
        }
    }
#undef DOTROW
}

// ---------------------------------------------------------------------------
// Persistent fused attention. Block j owns flattened rows [S, S+Len); slices
// cross at most one batch boundary. Key vectors live in smem (frees 16 regs
// -> 4 blocks/SM). Warps keep online-softmax state, flush per-segment into
// smem, block merges 8 warps -> <=2 global partials, last-arriving block per
// batch does the split-KV combine. attend_to is read from HBM exactly once.
// No spin-waits anywhere: cannot deadlock regardless of residency.
// ---------------------------------------------------------------------------
__global__ void __launch_bounds__(256, 4) attn_pass(
    const float* __restrict__ A, const void* __restrict__ mask_raw,
    float* __restrict__ out)
{
    const int j    = blockIdx.x;
    const int G    = gridDim.x;
    const int tid  = threadIdx.x;
    const int w    = tid >> 5;
    const int lane = tid & 31;

    const int L    = ROWS / G;
    const int rem  = ROWS % G;
    const int S    = (j < rem) ? j * (L + 1) : rem * (L + 1) + (j - rem) * L;
    const int Len  = (j < rem) ? (L + 1) : L;
    const int Eblk = S + Len;
    const int bF   = S >> 12;               // block's first batch
    const int bL   = (Eblk - 1) >> 12;      // block's last batch
    const int has2 = (bL != bF);

    // ---- per-block mask dtype self-detection (256-word sample):
    // random bool bytes make an int32 word >1 with p=7/8 per word.
    const unsigned int* mwords = (const unsigned int*)mask_raw;
    const int u8 = __syncthreads_or((int)(mwords[(j * 256 + tid) & 65535] > 1u));
    const unsigned char* __restrict__ m8  = (const unsigned char*)mask_raw;
    const int*           __restrict__ m32 = (const int*)mask_raw;

    __shared__ float sm_k[2][DD];
    __shared__ float sm_m[2][NWARP];
    __shared__ float sm_s[2][NWARP];
    __shared__ float sm_ctx[2][NWARP][DD];
    __shared__ unsigned int s_o0, s_o1;

    // stage both candidate key rows (bL may equal bF; harmless duplicate)
    sm_k[0][tid]       = g_k[bF * DD + tid];
    sm_k[0][tid + 256] = g_k[bF * DD + tid + 256];
    sm_k[1][tid]       = g_k[bL * DD + tid];
    sm_k[1][tid + 256] = g_k[bL * DD + tid + 256];

    // warp-local zeroing of this warp's partial slots (both segments)
#pragma unroll
    for (int sg = 0; sg < 2; sg++) {
        if (lane == 0) { sm_m[sg][w] = -CUDART_INF_F; sm_s[sg][w] = 0.f; }
        for (int i = lane; i < DD / 4; i += 32)
            ((float4*)sm_ctx[sg][w])[i] = make_float4(0.f, 0.f, 0.f, 0.f);
    }
    __syncthreads();

    int r    = S + w;
    int bcur = bF;
    const float* kptr = &sm_k[0][lane * 4];

    float m = -CUDART_INF_F, s = 0.f;
    float4 cx0 = make_float4(0.f, 0.f, 0.f, 0.f);
    float4 cx1 = cx0, cx2 = cx0, cx3 = cx0;

    float4 a0, a1, a2, a3, n0, n1, n2, n3;
    unsigned char mk, mkn;

#define PREFETCH(D0, D1, D2, D3, DM, RC)                                      \
    {   const float* _p = A + (size_t)(RC) * DD + lane * 4;                   \
        D0 = *(const float4*)(_p);                                            \
        D1 = *(const float4*)(_p + 128);                                      \
        D2 = *(const float4*)(_p + 256);                                      \
        D3 = *(const float4*)(_p + 384);                                      \
        const int _t = (RC) & 4095, _b = (RC) >> 12;                          \
        if (u8) DM = m8[_t * BB + _b];                                        \
        else    DM = (unsigned char)(m32[_t * BB + _b] != 0); }

#define PROCESS(A0, A1, A2, A3, MK)                                           \
    {   const float4 k0 = *(const float4*)(kptr);                             \
        const float4 k1 = *(const float4*)(kptr + 128);                       \
        const float4 k2 = *(const float4*)(kptr + 256);                       \
        const float4 k3 = *(const float4*)(kptr + 384);                       \
        float d0 = A0.x * k0.x; d0 = fmaf(A0.y, k0.y, d0);                    \
        d0 = fmaf(A0.z, k0.z, d0); d0 = fmaf(A0.w, k0.w, d0);                 \
        float d1 = A1.x * k1.x; d1 = fmaf(A1.y, k1.y, d1);                    \
        d1 = fmaf(A1.z, k1.z, d1); d1 = fmaf(A1.w, k1.w, d1);                 \
        float d2 = A2.x * k2.x; d2 = fmaf(A2.y, k2.y, d2);                    \
        d2 = fmaf(A2.z, k2.z, d2); d2 = fmaf(A2.w, k2.w, d2);                 \
        float d3 = A3.x * k3.x; d3 = fmaf(A3.y, k3.y, d3);                    \
        d3 = fmaf(A3.z, k3.z, d3); d3 = fmaf(A3.w, k3.w, d3);                 \
        float v = (d0 + d1) + (d2 + d3);                                      \
        v += __shfl_xor_sync(0xffffffffu, v, 16);                             \
        v += __shfl_xor_sync(0xffffffffu, v, 8);                              \
        v += __shfl_xor_sync(0xffffffffu, v, 4);                              \
        v += __shfl_xor_sync(0xffffffffu, v, 2);                              \
        v += __shfl_xor_sync(0xffffffffu, v, 1);                              \
        const float sc = (MK) ? -CUDART_INF_F : v;                            \
        if (sc > m) {                                                         \
            const float f = __expf(m - sc);                                   \
            s *= f;                                                           \
            cx0.x *= f; cx0.y *= f; cx0.z *= f; cx0.w *= f;                   \
            cx1.x *= f; cx1.y *= f; cx1.z *= f; cx1.w *= f;                   \
            cx2.x *= f; cx2.y *= f; cx2.z *= f; cx2.w *= f;                   \
            cx3.x *= f; cx3.y *= f; cx3.z *= f; cx3.w *= f;                   \
            m = sc;                                                           \
        }                                                                     \
        const float p = (sc == -CUDART_INF_F) ? 0.f : __expf(sc - m);         \
        s += p;                                                               \
        cx0.x = fmaf(p, A0.x, cx0.x); cx0.y = fmaf(p, A0.y, cx0.y);           \
        cx0.z = fmaf(p, A0.z, cx0.z); cx0.w = fmaf(p, A0.w, cx0.w);           \
        cx1.x = fmaf(p, A1.x, cx1.x); cx1.y = fmaf(p, A1.y, cx1.y);           \
        cx1.z = fmaf(p, A1.z, cx1.z); cx1.w = fmaf(p, A1.w, cx1.w);           \
        cx2.x = fmaf(p, A2.x, cx2.x); cx2.y = fmaf(p, A2.y, cx2.y);           \
        cx2.z = fmaf(p, A2.z, cx2.z); cx2.w = fmaf(p, A2.w, cx2.w);           \
        cx3.x = fmaf(p, A3.x, cx3.x); cx3.y = fmaf(p, A3.y, cx3.y);           \
        cx3.z = fmaf(p, A3.z, cx3.z); cx3.w = fmaf(p, A3.w, cx3.w); }

#define FLUSH()                                                               \
    {   const int _sg = (bcur == bF) ? 0 : 1;                                 \
        if (lane == 0) { sm_m[_sg][w] = m; sm_s[_sg][w] = s; }                \
        float* _cp = &sm_ctx[_sg][w][lane * 4];                               \
        *(float4*)(_cp)       = cx0;                                          \
        *(float4*)(_cp + 128) = cx1;                                          \
        *(float4*)(_cp + 256) = cx2;                                          \
        *(float4*)(_cp + 384) = cx3; }

#define BOUNDARY()                                                            \
    {   const int _bn = r >> 12;                                              \
        if (_bn != bcur) {                                                    \
            FLUSH();                                                          \
            m = -CUDART_INF_F; s = 0.f;                                       \
            cx0 = make_float4(0.f, 0.f, 0.f, 0.f);                            \
            cx1 = cx0; cx2 = cx0; cx3 = cx0;                                  \
            kptr = &sm_k[1][lane * 4];                                        \
            bcur = _bn; } }

    PREFETCH(a0, a1, a2, a3, mk, r);
    for (;;) {
        // half 1: process a (row r), prefetch r+8 into n
        int rn = r + NWARP;
        int rc = (rn < ROWS) ? rn : (ROWS - 1);
        PREFETCH(n0, n1, n2, n3, mkn, rc);
        PROCESS(a0, a1, a2, a3, mk);
        r = rn;
        if (r >= Eblk) break;
        BOUNDARY();
        // half 2: process n (row r), prefetch r+8 into a
        rn = r + NWARP;
        rc = (rn < ROWS) ? rn : (ROWS - 1);
        PREFETCH(a0, a1, a2, a3, mk, rc);
        PROCESS(n0, n1, n2, n3, mkn);
        r = rn;
        if (r >= Eblk) break;
        BOUNDARY();
    }
    FLUSH();
    __syncthreads();

    // ---- block merge: 8 warp partials -> 1 global partial per segment ----
#pragma unroll
    for (int sg = 0; sg < 2; sg++) {
        if (sg == 1 && !has2) break;
        float mstar = -CUDART_INF_F;
#pragma unroll
        for (int ww = 0; ww < NWARP; ww++) mstar = fmaxf(mstar, sm_m[sg][ww]);
        float den = 0.f, acc0 = 0.f, acc1 = 0.f;
#pragma unroll
        for (int ww = 0; ww < NWARP; ww++) {
            const float mw2 = sm_m[sg][ww];
            const float ew = (mw2 == -CUDART_INF_F) ? 0.f : __expf(mw2 - mstar);
            den  = fmaf(sm_s[sg][ww], ew, den);
            acc0 = fmaf(sm_ctx[sg][ww][tid],       ew, acc0);
            acc1 = fmaf(sm_ctx[sg][ww][tid + 256], ew, acc1);
        }
        const int slot = j * 2 + sg;
        if (tid == 0) { g_pm[slot] = mstar; g_ps[slot] = den; }
        g_pctx[(size_t)slot * DD + tid]       = acc0;
        g_pctx[(size_t)slot * DD + tid + 256] = acc1;
    }

    // ---- arrive; last block per batch combines ----
    __threadfence();
    __syncthreads();
    if (tid == 0) {
        s_o0 = atomicAdd(&g_cnt[bF], 1u);
        if (has2) s_o1 = atomicAdd(&g_cnt[bL], 1u);
    }
    __syncthreads();

    const int t1 = rem * (L + 1);
#define J_OF(rr)  (((rr) < t1) ? (rr) / (L + 1) : rem + ((rr) - t1) / L)
#define S_OF(jj)  (((jj) < rem) ? (jj) * (L + 1) : t1 + ((jj) - rem) * L)

#pragma unroll
    for (int which = 0; which < 2; which++) {
        if (which == 1 && !has2) break;
        const int b   = (which == 0) ? bF : bL;
        const int jlo = J_OF(b << 12);
        const int jhi = J_OF(((b + 1) << 12) - 1);
        const unsigned int expect = (unsigned int)(jhi - jlo + 1);
        const unsigned int got = (which == 0) ? s_o0 : s_o1;
        if (got != expect - 1) continue;

        __threadfence();   // acquire all contributors' partials

        float mg = -CUDART_INF_F;
        for (int jj = jlo; jj <= jhi; jj++) {
            const int sg = ((S_OF(jj) >> 12) == b) ? 0 : 1;
            mg = fmaxf(mg, g_pm[jj * 2 + sg]);
        }
        float den = 0.f, o0 = 0.f, o1 = 0.f;
        for (int jj = jlo; jj <= jhi; jj++) {
            const int sg = ((S_OF(jj) >> 12) == b) ? 0 : 1;
            const int sl = jj * 2 + sg;
            const float mi = g_pm[sl];
            const float e  = (mi == -CUDART_INF_F) ? 0.f : __expf(mi - mg);
            den = fmaf(g_ps[sl], e, den);
            o0  = fmaf(g_pctx[(size_t)sl * DD + tid],       e, o0);
            o1  = fmaf(g_pctx[(size_t)sl * DD + tid + 256], e, o1);
        }
        const float inv = 1.f / den;
        out[b * DD + tid]       = o0 * inv;
        out[b * DD + tid + 256] = o1 * inv;
    }
#undef J_OF
#undef S_OF
}

// ---------------------------------------------------------------------------
// Launch contract
// Inputs (metadata order): query[B,D] f32, attend_to[B,T,D] f32,
//                          mask[T,B] bool, W[D,D] f32, b[D] f32
// Output: context[B,1,D] f32
// ---------------------------------------------------------------------------
extern "C" void kernel_launch(void* const* d_in, const int* in_sizes, int n_in,
                              void* d_out, int out_size)
{
    (void)in_sizes; (void)n_in; (void)out_size;
    const float* q    = (const float*)d_in[0];
    const float* A    = (const float*)d_in[1];
    const void*  mask = d_in[2];
    const float* W    = (const float*)d_in[3];
    const float* bias = (const float*)d_in[4];
    float* out = (float*)d_out;

    int sms = 0;
    if (cudaDeviceGetAttribute(&sms, cudaDevAttrMultiProcessorCount, 0)
            != cudaSuccess || sms <= 0)
        sms = 152;                 // GB300 (R8 profile: grid 456 = 152*3)
    int grid = sms * 3;            // 456-way split: balanced, <=1 boundary/blk
    if (grid > MAXG) grid = MAXG;

    setup_kernel<<<BB, 256>>>(q, W, bias);
    attn_pass<<<grid, 256>>>(A, mask, out);
}